// round 16
// baseline (speedup 1.0000x reference)
#include <cuda_runtime.h>
#include <cuda_bf16.h>
#include <cstdint>
#include <cstddef>

#define NN 100000
#define NE 1600000
#define DD 128
#define PITCHB 272   // bf16 tile row pitch in bytes (128*2 + 16): conflict-free ldmatrix
#define MT 64        // M tile rows

// ---------------- scratch (device globals: no allocation allowed) ----------
__device__ float g_H[(size_t)NN * DD];   // x+agg (then Z2)
__device__ float g_Z[(size_t)NN * DD];   // Z1
__device__ float g_sum1[DD], g_sq1[DD], g_sum2[DD], g_sq2[DD];
__device__ int   g_is64;
__device__ __nv_bfloat16 g_Whi[3][DD * DD];
__device__ __nv_bfloat16 g_Wlo[3][DD * DD];
__device__ int g_off[NN + 1];   // CSR offsets (by dst)
__device__ int g_pos[NN];       // counts, then running cursors
__device__ int g_srcs[NE];      // CSR src lists

__device__ __forceinline__ uint32_t smem_u32(const void* p) {
    uint32_t a;
    asm("{ .reg .u64 t; cvta.to.shared.u64 t, %1; cvt.u32.u64 %0, t; }"
        : "=r"(a) : "l"(p));
    return a;
}

__device__ __forceinline__ void ldsm4(uint32_t* d, uint32_t addr) {
    asm volatile("ldmatrix.sync.aligned.m8n8.x4.shared.b16 {%0,%1,%2,%3}, [%4];"
                 : "=r"(d[0]), "=r"(d[1]), "=r"(d[2]), "=r"(d[3]) : "r"(addr));
}

__device__ __forceinline__ void mma16816(float* c, const uint32_t* a,
                                         uint32_t b0, uint32_t b1) {
    asm volatile(
        "mma.sync.aligned.m16n8k16.row.col.f32.bf16.bf16.f32 "
        "{%0,%1,%2,%3}, {%4,%5,%6,%7}, {%8,%9}, {%0,%1,%2,%3};"
        : "+f"(c[0]), "+f"(c[1]), "+f"(c[2]), "+f"(c[3])
        : "r"(a[0]), "r"(a[1]), "r"(a[2]), "r"(a[3]), "r"(b0), "r"(b1));
}

// ---------------- prep: zero stats + detect edge index dtype ---------------
__global__ void prep(const unsigned long long* __restrict__ ei) {
    int t = threadIdx.x;  // 128 threads
    g_sum1[t] = 0.f; g_sq1[t] = 0.f; g_sum2[t] = 0.f; g_sq2[t] = 0.f;
    if (t == 0) {
        // int64 edge data: every u64 word < NN. int32: two fused ints >= 2^32.
        int is64 = 1;
        for (int i = 0; i < 256; i++)
            if (ei[i] >= (unsigned long long)NN) { is64 = 0; break; }
        g_is64 = is64;
    }
}

// ---------------- convW: split all 3 weight matrices to bf16 hi/lo ---------
__global__ void convW(const float* __restrict__ W1, const float* __restrict__ W2,
                      const float* __restrict__ W3) {
    int i = blockIdx.x * blockDim.x + threadIdx.x;  // 0 .. 3*16384-1
    if (i >= 3 * DD * DD) return;
    int layer = i / (DD * DD), j = i % (DD * DD);
    const float* Ws = (layer == 0) ? W1 : (layer == 1) ? W2 : W3;
    float v = Ws[j];
    __nv_bfloat16 h = __float2bfloat16_rn(v);
    __nv_bfloat16 l = __float2bfloat16_rn(v - __bfloat162float(h));
    g_Whi[layer][j] = h;
    g_Wlo[layer][j] = l;
}

// ================ CSR build: hist -> scan -> reorder ========================
__global__ void hist(const void* __restrict__ ei) {
    int e = blockIdx.x * 256 + threadIdx.x;
    if (e >= NE) return;
    int dst = g_is64 ? (int)((const long long*)ei)[NE + e]
                     : ((const int*)ei)[NE + e];
    atomicAdd(&g_pos[dst], 1);
}

// single block, 1024 threads: exclusive scan of counts -> g_off and cursors
__global__ void __launch_bounds__(1024) scan_k() {
    __shared__ int partial[1024];
    __shared__ int wsum[32];
    const int C = (NN + 1023) / 1024;  // 98
    int t = threadIdx.x;
    int b = t * C;
    int e_ = min(b + C, NN);
    int s = 0;
    for (int i = b; i < e_; i++) s += g_pos[i];
    partial[t] = s;
    __syncthreads();
    int lane = t & 31, wid = t >> 5;
    int v = partial[t];
    #pragma unroll
    for (int d = 1; d < 32; d <<= 1) {
        int u = __shfl_up_sync(0xffffffffu, v, d);
        if (lane >= d) v += u;
    }
    if (lane == 31) wsum[wid] = v;
    __syncthreads();
    if (wid == 0) {
        int w = wsum[lane];
        #pragma unroll
        for (int d = 1; d < 32; d <<= 1) {
            int u = __shfl_up_sync(0xffffffffu, w, d);
            if (lane >= d) w += u;
        }
        wsum[lane] = w;
    }
    __syncthreads();
    int excl = v - partial[t] + (wid ? wsum[wid - 1] : 0);
    int run = excl;
    for (int i = b; i < e_; i++) {
        int c = g_pos[i];
        g_off[i] = run;
        g_pos[i] = run;
        run += c;
    }
    if (t == 1023) g_off[NN] = run;  // = NE
}

__global__ void reorder(const void* __restrict__ ei) {
    int e = blockIdx.x * 256 + threadIdx.x;
    if (e >= NE) return;
    int src, dst;
    if (g_is64) {
        const long long* p = (const long long*)ei;
        src = (int)p[e];
        dst = (int)p[NE + e];
    } else {
        const int* p = (const int*)ei;
        src = p[e];
        dst = p[NE + e];
    }
    int pp = atomicAdd(&g_pos[dst], 1);
    g_srcs[pp] = src;
}

// ---------------- gather: H[i] = x[i] + sum_{j->i} x[j] (warp per node) ----
__global__ void __launch_bounds__(256) gather(const float4* __restrict__ x) {
    int node = blockIdx.x * 8 + (threadIdx.x >> 5);
    if (node >= NN) return;
    int lane = threadIdx.x & 31;
    int beg = g_off[node], end = g_off[node + 1];
    float4 acc = __ldg(x + (size_t)node * 32 + lane);  // GIN self term (eps=0)
    for (int e = beg; e < end; e += 32) {
        int cnt = min(32, end - e);
        int s = (lane < cnt) ? __ldg(&g_srcs[e + lane]) : 0;
        int j = 0;
        for (; j + 4 <= cnt; j += 4) {
            int s0 = __shfl_sync(0xffffffffu, s, j);
            int s1 = __shfl_sync(0xffffffffu, s, j + 1);
            int s2 = __shfl_sync(0xffffffffu, s, j + 2);
            int s3 = __shfl_sync(0xffffffffu, s, j + 3);
            float4 v0 = __ldg(x + (size_t)s0 * 32 + lane);
            float4 v1 = __ldg(x + (size_t)s1 * 32 + lane);
            float4 v2 = __ldg(x + (size_t)s2 * 32 + lane);
            float4 v3 = __ldg(x + (size_t)s3 * 32 + lane);
            acc.x += v0.x + v1.x + v2.x + v3.x;
            acc.y += v0.y + v1.y + v2.y + v3.y;
            acc.z += v0.z + v1.z + v2.z + v3.z;
            acc.w += v0.w + v1.w + v2.w + v3.w;
        }
        for (; j < cnt; j++) {
            int sj = __shfl_sync(0xffffffffu, s, j);
            float4 v = __ldg(x + (size_t)sj * 32 + lane);
            acc.x += v.x; acc.y += v.y; acc.z += v.z; acc.w += v.w;
        }
    }
    ((float4*)g_H)[(size_t)node * 32 + lane] = acc;
}

// ======================= mma.sync fused GEMM ================================
// Z = transform(A) @ W^T (+bias) (+col stats), fp32 via bf16 hi/lo split:
//   A@W ~= Ahi@Whi + Ahi@Wlo + Alo@Whi  (fp32 accum, single merged k-loop)
// mode 0: A' = A;                            out = A'@W^T + b; stats
// mode 1: A' = relu(A*sc+sh), BN from stats; out = A'@W^T + b; stats
// mode 2: A' = relu(A*sc+sh), BN from stats; out = relu(A'@W^T)
#define TILE_A (MT * PITCHB)             // 17408
#define TILE_W (DD * PITCHB)             // 34816
#define SMO_SSUM (2 * TILE_A + 2 * TILE_W)
#define SMO_SSQ  (SMO_SSUM + 4 * DD * 4)
#define SMO_SC   (SMO_SSQ + 4 * DD * 4)
#define SMO_SH   (SMO_SC + DD * 4)
#define SMEM_BYTES (SMO_SH + DD * 4)     // 109568

__device__ __forceinline__ void split_store(char* hi, char* lo,
                                            int row, int k4, float4 v) {
    int off = row * PITCHB + k4 * 8;
    __nv_bfloat162 h0 = __floats2bfloat162_rn(v.x, v.y);
    __nv_bfloat162 h1 = __floats2bfloat162_rn(v.z, v.w);
    float lx = v.x - __bfloat162float(h0.x);
    float ly = v.y - __bfloat162float(h0.y);
    float lz = v.z - __bfloat162float(h1.x);
    float lw = v.w - __bfloat162float(h1.y);
    __nv_bfloat162 l0 = __floats2bfloat162_rn(lx, ly);
    __nv_bfloat162 l1 = __floats2bfloat162_rn(lz, lw);
    *(uint2*)(hi + off) = make_uint2(*(uint32_t*)&h0, *(uint32_t*)&h1);
    *(uint2*)(lo + off) = make_uint2(*(uint32_t*)&l0, *(uint32_t*)&l1);
}

__global__ void __launch_bounds__(256, 2) gemm_mma(
    const float* __restrict__ A,
    const __nv_bfloat16* __restrict__ Wghi, const __nv_bfloat16* __restrict__ Wglo,
    const float* __restrict__ bias,
    const float* __restrict__ gamma, const float* __restrict__ beta,
    const float* __restrict__ gsumIn, const float* __restrict__ gsqIn,
    float* __restrict__ Z, float* __restrict__ gsum, float* __restrict__ gsq,
    int mode)
{
    extern __shared__ char sm[];
    char* Ahi = sm;
    char* Alo = sm + TILE_A;
    char* Whi = sm + 2 * TILE_A;
    char* Wlo = sm + 2 * TILE_A + TILE_W;
    float* sSum   = (float*)(sm + SMO_SSUM);
    float* sSq    = (float*)(sm + SMO_SSQ);
    float* sScale = (float*)(sm + SMO_SC);
    float* sShift = (float*)(sm + SMO_SH);

    int tid = threadIdx.x;
    int rowBase = blockIdx.x * MT;

    // ---- fold BN into (scale, shift) from the previous layer's stats ----
    if (mode != 0 && tid < DD) {
        float mean = __ldg(gsumIn + tid) * (1.0f / NN);
        float var  = fmaxf(__ldg(gsqIn + tid) * (1.0f / NN) - mean * mean, 0.f);
        float sc   = __ldg(gamma + tid) * rsqrtf(var + 1e-5f);
        sScale[tid] = sc;
        sShift[tid] = __ldg(beta + tid) - mean * sc;
    }
    // ---- copy pre-split W (bf16) into pitched smem: 2048 uint4 per tile ----
    #pragma unroll
    for (int it = 0; it < 8; ++it) {
        int idx = it * 256 + tid;            // 0..2047
        int n = idx >> 4, u = idx & 15;      // row, 16B chunk
        uint4 v = __ldg((const uint4*)Wghi + idx);
        *(uint4*)(Whi + n * PITCHB + u * 16) = v;
        uint4 w = __ldg((const uint4*)Wglo + idx);
        *(uint4*)(Wlo + n * PITCHB + u * 16) = w;
    }
    if (mode != 0) __syncthreads();  // sScale/sShift ready before A transform

    // ---- A[m][k] fp32 (+transform) -> bf16 hi/lo tiles (64 rows) ----
    #pragma unroll
    for (int it = 0; it < 8; ++it) {
        int idx = it * 256 + tid;            // 0..2047
        int m = idx >> 5, k4 = idx & 31;
        int row = rowBase + m;
        float4 v = make_float4(0.f, 0.f, 0.f, 0.f);
        if (row < NN) {
            v = __ldg((const float4*)A + (size_t)row * 32 + k4);
            if (mode != 0) {
                float4 s = ((const float4*)sScale)[k4];
                float4 t = ((const float4*)sShift)[k4];
                v.x = fmaxf(fmaf(v.x, s.x, t.x), 0.f);
                v.y = fmaxf(fmaf(v.y, s.y, t.y), 0.f);
                v.z = fmaxf(fmaf(v.z, s.z, t.z), 0.f);
                v.w = fmaxf(fmaf(v.w, s.w, t.w), 0.f);
            }
        }
        split_store(Ahi, Alo, m, k4, v);
    }
    __syncthreads();

    int wid = tid >> 5, lane = tid & 31;
    int mw = (wid >> 1) * 16;     // warp's 16-row slab
    int nw = (wid & 1) * 64;      // warp's 64-col slab

    float acc[8][4];
    #pragma unroll
    for (int na = 0; na < 8; na++)
        #pragma unroll
        for (int j = 0; j < 4; j++) acc[na][j] = 0.f;

    int r = lane & 7, sel = lane >> 3;
    // ldmatrix lane addressing:
    //  A x4: mats {rows m0-7@k0, m8-15@k0, m0-7@k8, m8-15@k8}
    //  W x4: mats {rows n0-7@k0, n0-7@k8, n8-15@k0, n8-15@k8}
    uint32_t aOff = (uint32_t)((mw + r + (sel & 1) * 8) * PITCHB + (sel >> 1) * 16);
    uint32_t bOff = (uint32_t)((nw + r + (sel >> 1) * 8) * PITCHB + (sel & 1) * 16);
    uint32_t aHiA = smem_u32(Ahi) + aOff, aLoA = smem_u32(Alo) + aOff;
    uint32_t bHiA = smem_u32(Whi) + bOff, bLoA = smem_u32(Wlo) + bOff;

    // merged k-loop: per k-step load a_hi,a_lo + b_hi,b_lo once, 24 MMAs
    #pragma unroll
    for (int ks = 0; ks < 8; ks++) {
        uint32_t ko = ks * 32;  // 16 bf16 = 32 bytes per K-step
        uint32_t ah[4], al[4], bh[4][4], bl[4][4];
        ldsm4(ah, aHiA + ko);
        ldsm4(al, aLoA + ko);
        #pragma unroll
        for (int ng = 0; ng < 4; ng++) {
            ldsm4(bh[ng], bHiA + ng * 16 * PITCHB + ko);
            ldsm4(bl[ng], bLoA + ng * 16 * PITCHB + ko);
        }
        #pragma unroll
        for (int na = 0; na < 8; na++) {
            uint32_t b0h = bh[na >> 1][(na & 1) * 2];
            uint32_t b1h = bh[na >> 1][(na & 1) * 2 + 1];
            uint32_t b0l = bl[na >> 1][(na & 1) * 2];
            uint32_t b1l = bl[na >> 1][(na & 1) * 2 + 1];
            mma16816(acc[na], ah, b0h, b1h);
            mma16816(acc[na], ah, b0l, b1l);
            mma16816(acc[na], al, b0h, b1h);
        }
    }

    // ---- epilogue. D-frag: c0,c1 -> (row l/4, col 2(l&3)+{0,1}); c2,c3 -> row+8
    int qr = lane >> 2, qc = lane & 3;
    int row0 = rowBase + mw + qr;
    int row1 = row0 + 8;
    bool ok0 = row0 < NN, ok1 = row1 < NN;
    float* o0 = Z + (size_t)row0 * DD + nw + qc * 2;
    float* o1 = Z + (size_t)row1 * DD + nw + qc * 2;

    if (mode == 2) {
        #pragma unroll
        for (int na = 0; na < 8; na++) {
            float* c = acc[na];
            if (ok0) *(float2*)(o0 + na * 8) =
                make_float2(fmaxf(c[0], 0.f), fmaxf(c[1], 0.f));
            if (ok1) *(float2*)(o1 + na * 8) =
                make_float2(fmaxf(c[2], 0.f), fmaxf(c[3], 0.f));
        }
    } else {
        float csum[16], csq[16];
        #pragma unroll
        for (int na = 0; na < 8; na++) {
            float2 bv = __ldg((const float2*)(bias + nw + na * 8 + qc * 2));
            float z0 = acc[na][0] + bv.x;
            float z1 = acc[na][1] + bv.y;
            float z2 = acc[na][2] + bv.x;
            float z3 = acc[na][3] + bv.y;
            if (ok0) *(float2*)(o0 + na * 8) = make_float2(z0, z1);
            if (ok1) *(float2*)(o1 + na * 8) = make_float2(z2, z3);
            float t0 = ok0 ? z0 : 0.f, t1 = ok0 ? z1 : 0.f;
            float t2 = ok1 ? z2 : 0.f, t3 = ok1 ? z3 : 0.f;
            csum[na * 2]     = t0 + t2;
            csum[na * 2 + 1] = t1 + t3;
            csq[na * 2]      = t0 * t0 + t2 * t2;
            csq[na * 2 + 1]  = t1 * t1 + t3 * t3;
        }
        // reduce over the 8 row-quads (lane bits 2..4)
        #pragma unroll
        for (int mask = 4; mask <= 16; mask <<= 1) {
            #pragma unroll
            for (int j = 0; j < 16; j++) {
                csum[j] += __shfl_xor_sync(0xffffffffu, csum[j], mask);
                csq[j]  += __shfl_xor_sync(0xffffffffu, csq[j], mask);
            }
        }
        int g = wid >> 1;  // 4 row groups; warps 2g/2g+1 cover disjoint cols
        if (lane < 4) {
            #pragma unroll
            for (int na = 0; na < 8; na++) {
                int col = nw + na * 8 + lane * 2;
                sSum[g * DD + col]     = csum[na * 2];
                sSum[g * DD + col + 1] = csum[na * 2 + 1];
                sSq [g * DD + col]     = csq[na * 2];
                sSq [g * DD + col + 1] = csq[na * 2 + 1];
            }
        }
        __syncthreads();
        if (tid < DD) {
            float s = sSum[tid] + sSum[DD + tid] + sSum[2 * DD + tid] + sSum[3 * DD + tid];
            atomicAdd(&gsum[tid], s);
        } else if (tid < 2 * DD) {
            int n = tid - DD;
            float s = sSq[n] + sSq[DD + n] + sSq[2 * DD + n] + sSq[3 * DD + n];
            atomicAdd(&gsq[n], s);
        }
    }
}

// ---------------- launch ----------------------------------------------------
extern "C" void kernel_launch(void* const* d_in, const int* in_sizes, int n_in,
                              void* d_out, int out_size) {
    const float* x   = (const float*)d_in[0];
    const void*  ei  = d_in[1];
    const float* W1  = (const float*)d_in[2];
    const float* b1  = (const float*)d_in[3];
    const float* g1  = (const float*)d_in[4];
    const float* be1 = (const float*)d_in[5];
    const float* W2  = (const float*)d_in[6];
    const float* b2  = (const float*)d_in[7];
    const float* g2  = (const float*)d_in[8];
    const float* be2 = (const float*)d_in[9];
    const float* W3  = (const float*)d_in[10];
    float* out = (float*)d_out;

    float *H, *Z, *s1, *q1, *s2, *q2;
    __nv_bfloat16 *Whi, *Wlo;
    int *pos;
    cudaGetSymbolAddress((void**)&H,   g_H);
    cudaGetSymbolAddress((void**)&Z,   g_Z);
    cudaGetSymbolAddress((void**)&s1,  g_sum1);
    cudaGetSymbolAddress((void**)&q1,  g_sq1);
    cudaGetSymbolAddress((void**)&s2,  g_sum2);
    cudaGetSymbolAddress((void**)&q2,  g_sq2);
    cudaGetSymbolAddress((void**)&Whi, g_Whi);
    cudaGetSymbolAddress((void**)&Wlo, g_Wlo);
    cudaGetSymbolAddress((void**)&pos, g_pos);

    cudaFuncSetAttribute(gemm_mma, cudaFuncAttributeMaxDynamicSharedMemorySize,
                         SMEM_BYTES);

    // 1) zero stats/counters ; detect edge dtype ; pre-split weights
    cudaMemsetAsync(pos, 0, NN * sizeof(int));
    prep<<<1, 128>>>((const unsigned long long*)ei);
    convW<<<(3 * DD * DD + 255) / 256, 256>>>(W1, W2, W3);

    // 2) CSR build + gather:  H = x + segment_sum(x[src] by dst)
    hist<<<(NE + 255) / 256, 256>>>(ei);
    scan_k<<<1, 1024>>>();
    reorder<<<(NE + 255) / 256, 256>>>(ei);
    gather<<<(NN + 7) / 8, 256>>>((const float4*)x);

    int gblocks = (NN + MT - 1) / MT;  // 1563

    // 3) Z1 = H @ W1^T + b1, with column stats
    gemm_mma<<<gblocks, 256, SMEM_BYTES>>>(H, Whi, Wlo, b1,
                                           nullptr, nullptr, nullptr, nullptr,
                                           Z, s1, q1, 0);
    // 4) Z2 = relu(BN(Z1)) @ W2^T + b2, with column stats  (Z2 -> H buffer)
    gemm_mma<<<gblocks, 256, SMEM_BYTES>>>(Z, Whi + DD * DD, Wlo + DD * DD,
                                           b2, g1, be1, s1, q1,
                                           H, s2, q2, 1);
    // 5) out = relu( relu(BN(Z2)) @ W3^T )
    gemm_mma<<<gblocks, 256, SMEM_BYTES>>>(H, Whi + 2 * DD * DD, Wlo + 2 * DD * DD,
                                           nullptr, g2, be2, s2, q2,
                                           out, nullptr, nullptr, 2);
}

// round 17
// speedup vs baseline: 1.5062x; 1.5062x over previous
#include <cuda_runtime.h>
#include <cuda_bf16.h>
#include <cstdint>
#include <cstddef>

#define NN 100000
#define NE 1600000
#define DD 128
#define PITCHB 272   // bf16 tile row pitch in bytes (128*2 + 16): conflict-free ldmatrix
#define MT 64        // M tile rows
#define SCAN_BLKS ((NN + 1023) / 1024)   // 98

// ---------------- scratch (device globals: no allocation allowed) ----------
__device__ float g_H[(size_t)NN * DD];   // x+agg (then Z2)
__device__ float g_Z[(size_t)NN * DD];   // Z1
__device__ float g_sum1[DD], g_sq1[DD], g_sum2[DD], g_sq2[DD];
__device__ int   g_is64;
__device__ __nv_bfloat16 g_Whi[3][DD * DD];
__device__ __nv_bfloat16 g_Wlo[3][DD * DD];
__device__ int g_off[NN + 1];   // CSR offsets (by dst)
__device__ int g_pos[NN];       // counts, then running cursors
__device__ int g_srcs[NE];      // CSR src lists
__device__ int g_bsum[128];     // per-block count sums (scan)

__device__ __forceinline__ uint32_t smem_u32(const void* p) {
    uint32_t a;
    asm("{ .reg .u64 t; cvta.to.shared.u64 t, %1; cvt.u32.u64 %0, t; }"
        : "=r"(a) : "l"(p));
    return a;
}

__device__ __forceinline__ void ldsm4(uint32_t* d, uint32_t addr) {
    asm volatile("ldmatrix.sync.aligned.m8n8.x4.shared.b16 {%0,%1,%2,%3}, [%4];"
                 : "=r"(d[0]), "=r"(d[1]), "=r"(d[2]), "=r"(d[3]) : "r"(addr));
}

__device__ __forceinline__ void mma16816(float* c, const uint32_t* a,
                                         uint32_t b0, uint32_t b1) {
    asm volatile(
        "mma.sync.aligned.m16n8k16.row.col.f32.bf16.bf16.f32 "
        "{%0,%1,%2,%3}, {%4,%5,%6,%7}, {%8,%9}, {%0,%1,%2,%3};"
        : "+f"(c[0]), "+f"(c[1]), "+f"(c[2]), "+f"(c[3])
        : "r"(a[0]), "r"(a[1]), "r"(a[2]), "r"(a[3]), "r"(b0), "r"(b1));
}

// ---------------- prep: zero stats + detect edge index dtype ---------------
__global__ void prep(const unsigned long long* __restrict__ ei) {
    int t = threadIdx.x;  // 128 threads
    g_sum1[t] = 0.f; g_sq1[t] = 0.f; g_sum2[t] = 0.f; g_sq2[t] = 0.f;
    if (t == 0) {
        // int64 edge data: every u64 word < NN. int32: two fused ints >= 2^32.
        int is64 = 1;
        for (int i = 0; i < 256; i++)
            if (ei[i] >= (unsigned long long)NN) { is64 = 0; break; }
        g_is64 = is64;
        g_off[NN] = NE;
    }
}

// ---------------- convW: split all 3 weight matrices to bf16 hi/lo ---------
__global__ void convW(const float* __restrict__ W1, const float* __restrict__ W2,
                      const float* __restrict__ W3) {
    int i = blockIdx.x * blockDim.x + threadIdx.x;  // 0 .. 3*16384-1
    if (i >= 3 * DD * DD) return;
    int layer = i / (DD * DD), j = i % (DD * DD);
    const float* Ws = (layer == 0) ? W1 : (layer == 1) ? W2 : W3;
    float v = Ws[j];
    __nv_bfloat16 h = __float2bfloat16_rn(v);
    __nv_bfloat16 l = __float2bfloat16_rn(v - __bfloat162float(h));
    g_Whi[layer][j] = h;
    g_Wlo[layer][j] = l;
}

// ================ CSR build: hist -> 3-stage scan -> reorder ================
__global__ void hist(const void* __restrict__ ei) {
    int e = blockIdx.x * 256 + threadIdx.x;
    if (e >= NE) return;
    int dst = g_is64 ? (int)((const long long*)ei)[NE + e]
                     : ((const int*)ei)[NE + e];
    atomicAdd(&g_pos[dst], 1);
}

// stage 1: per-block sums of counts (grid = SCAN_BLKS, 1024 thr)
__global__ void __launch_bounds__(1024) blk_reduce() {
    __shared__ int wsum[32];
    int i = blockIdx.x * 1024 + threadIdx.x;
    int c = (i < NN) ? g_pos[i] : 0;
    int lane = threadIdx.x & 31, wid = threadIdx.x >> 5;
    #pragma unroll
    for (int d = 16; d >= 1; d >>= 1) c += __shfl_xor_sync(0xffffffffu, c, d);
    if (lane == 0) wsum[wid] = c;
    __syncthreads();
    if (wid == 0) {
        int v = wsum[lane];
        #pragma unroll
        for (int d = 16; d >= 1; d >>= 1) v += __shfl_xor_sync(0xffffffffu, v, d);
        if (lane == 0) g_bsum[blockIdx.x] = v;
    }
}

// stage 2: exclusive scan of SCAN_BLKS block sums (1 block, 128 thr)
__global__ void scan_small() {
    __shared__ int s[128];
    int t = threadIdx.x;
    s[t] = (t < SCAN_BLKS) ? g_bsum[t] : 0;
    __syncthreads();
    #pragma unroll
    for (int d = 1; d < 128; d <<= 1) {
        int v = (t >= d) ? s[t - d] : 0;
        __syncthreads();
        s[t] += v;
        __syncthreads();
    }
    if (t < SCAN_BLKS) g_bsum[t] = s[t] - ((t < SCAN_BLKS) ? 0 : 0) - (t < SCAN_BLKS ? (t == 0 ? s[0] : s[t] - s[t - 1]) : 0) + (t == 0 ? 0 : 0), g_bsum[t] = (t == 0) ? 0 : s[t - 1];
}

// stage 3: per-element exclusive scan within block + block base
__global__ void __launch_bounds__(1024) scan_final() {
    __shared__ int wsum[32];
    int i = blockIdx.x * 1024 + threadIdx.x;
    int lane = threadIdx.x & 31, wid = threadIdx.x >> 5;
    int c = (i < NN) ? g_pos[i] : 0;
    int v = c;
    #pragma unroll
    for (int d = 1; d < 32; d <<= 1) {
        int u = __shfl_up_sync(0xffffffffu, v, d);
        if (lane >= d) v += u;
    }
    if (lane == 31) wsum[wid] = v;
    __syncthreads();
    if (wid == 0) {
        int w = (lane < 32) ? wsum[lane] : 0;
        #pragma unroll
        for (int d = 1; d < 32; d <<= 1) {
            int u = __shfl_up_sync(0xffffffffu, w, d);
            if (lane >= d) w += u;
        }
        wsum[lane] = w;
    }
    __syncthreads();
    int excl = v - c + (wid ? wsum[wid - 1] : 0) + g_bsum[blockIdx.x];
    if (i < NN) {
        g_off[i] = excl;
        g_pos[i] = excl;
    }
}

__global__ void reorder(const void* __restrict__ ei) {
    int e = blockIdx.x * 256 + threadIdx.x;
    if (e >= NE) return;
    int src, dst;
    if (g_is64) {
        const long long* p = (const long long*)ei;
        src = (int)p[e];
        dst = (int)p[NE + e];
    } else {
        const int* p = (const int*)ei;
        src = p[e];
        dst = p[NE + e];
    }
    int pp = atomicAdd(&g_pos[dst], 1);
    g_srcs[pp] = src;
}

// ---------------- gather: H[i] = x[i] + sum_{j->i} x[j] (warp per node) ----
__global__ void __launch_bounds__(256) gather(const float4* __restrict__ x) {
    int node = blockIdx.x * 8 + (threadIdx.x >> 5);
    if (node >= NN) return;
    int lane = threadIdx.x & 31;
    int beg = g_off[node], end = g_off[node + 1];
    float4 acc = __ldg(x + (size_t)node * 32 + lane);  // GIN self term (eps=0)
    for (int e = beg; e < end; e += 32) {
        int cnt = min(32, end - e);
        int s = (lane < cnt) ? __ldg(&g_srcs[e + lane]) : 0;
        int j = 0;
        for (; j + 4 <= cnt; j += 4) {
            int s0 = __shfl_sync(0xffffffffu, s, j);
            int s1 = __shfl_sync(0xffffffffu, s, j + 1);
            int s2 = __shfl_sync(0xffffffffu, s, j + 2);
            int s3 = __shfl_sync(0xffffffffu, s, j + 3);
            float4 v0 = __ldg(x + (size_t)s0 * 32 + lane);
            float4 v1 = __ldg(x + (size_t)s1 * 32 + lane);
            float4 v2 = __ldg(x + (size_t)s2 * 32 + lane);
            float4 v3 = __ldg(x + (size_t)s3 * 32 + lane);
            acc.x += v0.x + v1.x + v2.x + v3.x;
            acc.y += v0.y + v1.y + v2.y + v3.y;
            acc.z += v0.z + v1.z + v2.z + v3.z;
            acc.w += v0.w + v1.w + v2.w + v3.w;
        }
        for (; j < cnt; j++) {
            int sj = __shfl_sync(0xffffffffu, s, j);
            float4 v = __ldg(x + (size_t)sj * 32 + lane);
            acc.x += v.x; acc.y += v.y; acc.z += v.z; acc.w += v.w;
        }
    }
    ((float4*)g_H)[(size_t)node * 32 + lane] = acc;
}

// ======================= mma.sync fused GEMM ================================
// Z = transform(A) @ W^T (+bias) (+col stats), fp32 via bf16 hi/lo split:
//   A@W ~= Ahi@Whi + Ahi@Wlo + Alo@Whi  (fp32 accum, single merged k-loop)
// mode 0: A' = A;                            out = A'@W^T + b; stats
// mode 1: A' = relu(A*sc+sh), BN from stats; out = A'@W^T + b; stats
// mode 2: A' = relu(A*sc+sh), BN from stats; out = relu(A'@W^T)
#define TILE_A (MT * PITCHB)             // 17408
#define TILE_W (DD * PITCHB)             // 34816
#define SMO_SSUM (2 * TILE_A + 2 * TILE_W)
#define SMO_SSQ  (SMO_SSUM + 4 * DD * 4)
#define SMO_SC   (SMO_SSQ + 4 * DD * 4)
#define SMO_SH   (SMO_SC + DD * 4)
#define SMEM_BYTES (SMO_SH + DD * 4)     // 109568

__device__ __forceinline__ void split_store(char* hi, char* lo,
                                            int row, int k4, float4 v) {
    int off = row * PITCHB + k4 * 8;
    __nv_bfloat162 h0 = __floats2bfloat162_rn(v.x, v.y);
    __nv_bfloat162 h1 = __floats2bfloat162_rn(v.z, v.w);
    float lx = v.x - __bfloat162float(h0.x);
    float ly = v.y - __bfloat162float(h0.y);
    float lz = v.z - __bfloat162float(h1.x);
    float lw = v.w - __bfloat162float(h1.y);
    __nv_bfloat162 l0 = __floats2bfloat162_rn(lx, ly);
    __nv_bfloat162 l1 = __floats2bfloat162_rn(lz, lw);
    *(uint2*)(hi + off) = make_uint2(*(uint32_t*)&h0, *(uint32_t*)&h1);
    *(uint2*)(lo + off) = make_uint2(*(uint32_t*)&l0, *(uint32_t*)&l1);
}

__global__ void __launch_bounds__(256, 2) gemm_mma(
    const float* __restrict__ A,
    const __nv_bfloat16* __restrict__ Wghi, const __nv_bfloat16* __restrict__ Wglo,
    const float* __restrict__ bias,
    const float* __restrict__ gamma, const float* __restrict__ beta,
    const float* __restrict__ gsumIn, const float* __restrict__ gsqIn,
    float* __restrict__ Z, float* __restrict__ gsum, float* __restrict__ gsq,
    int mode)
{
    extern __shared__ char sm[];
    char* Ahi = sm;
    char* Alo = sm + TILE_A;
    char* Whi = sm + 2 * TILE_A;
    char* Wlo = sm + 2 * TILE_A + TILE_W;
    float* sSum   = (float*)(sm + SMO_SSUM);
    float* sSq    = (float*)(sm + SMO_SSQ);
    float* sScale = (float*)(sm + SMO_SC);
    float* sShift = (float*)(sm + SMO_SH);

    int tid = threadIdx.x;
    int rowBase = blockIdx.x * MT;

    // ---- fold BN into (scale, shift) from the previous layer's stats ----
    if (mode != 0 && tid < DD) {
        float mean = __ldg(gsumIn + tid) * (1.0f / NN);
        float var  = fmaxf(__ldg(gsqIn + tid) * (1.0f / NN) - mean * mean, 0.f);
        float sc   = __ldg(gamma + tid) * rsqrtf(var + 1e-5f);
        sScale[tid] = sc;
        sShift[tid] = __ldg(beta + tid) - mean * sc;
    }
    // ---- copy pre-split W (bf16) into pitched smem: 2048 uint4 per tile ----
    #pragma unroll
    for (int it = 0; it < 8; ++it) {
        int idx = it * 256 + tid;            // 0..2047
        int n = idx >> 4, u = idx & 15;      // row, 16B chunk
        uint4 v = __ldg((const uint4*)Wghi + idx);
        *(uint4*)(Whi + n * PITCHB + u * 16) = v;
        uint4 w = __ldg((const uint4*)Wglo + idx);
        *(uint4*)(Wlo + n * PITCHB + u * 16) = w;
    }
    if (mode != 0) __syncthreads();  // sScale/sShift ready before A transform

    // ---- A[m][k] fp32 (+transform) -> bf16 hi/lo tiles (64 rows) ----
    #pragma unroll
    for (int it = 0; it < 8; ++it) {
        int idx = it * 256 + tid;            // 0..2047
        int m = idx >> 5, k4 = idx & 31;
        int row = rowBase + m;
        float4 v = make_float4(0.f, 0.f, 0.f, 0.f);
        if (row < NN) {
            v = __ldg((const float4*)A + (size_t)row * 32 + k4);
            if (mode != 0) {
                float4 s = ((const float4*)sScale)[k4];
                float4 t = ((const float4*)sShift)[k4];
                v.x = fmaxf(fmaf(v.x, s.x, t.x), 0.f);
                v.y = fmaxf(fmaf(v.y, s.y, t.y), 0.f);
                v.z = fmaxf(fmaf(v.z, s.z, t.z), 0.f);
                v.w = fmaxf(fmaf(v.w, s.w, t.w), 0.f);
            }
        }
        split_store(Ahi, Alo, m, k4, v);
    }
    __syncthreads();

    int wid = tid >> 5, lane = tid & 31;
    int mw = (wid >> 1) * 16;     // warp's 16-row slab
    int nw = (wid & 1) * 64;      // warp's 64-col slab

    float acc[8][4];
    #pragma unroll
    for (int na = 0; na < 8; na++)
        #pragma unroll
        for (int j = 0; j < 4; j++) acc[na][j] = 0.f;

    int r = lane & 7, sel = lane >> 3;
    // ldmatrix lane addressing:
    //  A x4: mats {rows m0-7@k0, m8-15@k0, m0-7@k8, m8-15@k8}
    //  W x4: mats {rows n0-7@k0, n0-7@k8, n8-15@k0, n8-15@k8}
    uint32_t aOff = (uint32_t)((mw + r + (sel & 1) * 8) * PITCHB + (sel >> 1) * 16);
    uint32_t bOff = (uint32_t)((nw + r + (sel >> 1) * 8) * PITCHB + (sel & 1) * 16);
    uint32_t aHiA = smem_u32(Ahi) + aOff, aLoA = smem_u32(Alo) + aOff;
    uint32_t bHiA = smem_u32(Whi) + bOff, bLoA = smem_u32(Wlo) + bOff;

    // merged k-loop: per k-step load a_hi,a_lo + b_hi,b_lo once, 24 MMAs
    #pragma unroll
    for (int ks = 0; ks < 8; ks++) {
        uint32_t ko = ks * 32;  // 16 bf16 = 32 bytes per K-step
        uint32_t ah[4], al[4], bh[4][4], bl[4][4];
        ldsm4(ah, aHiA + ko);
        ldsm4(al, aLoA + ko);
        #pragma unroll
        for (int ng = 0; ng < 4; ng++) {
            ldsm4(bh[ng], bHiA + ng * 16 * PITCHB + ko);
            ldsm4(bl[ng], bLoA + ng * 16 * PITCHB + ko);
        }
        #pragma unroll
        for (int na = 0; na < 8; na++) {
            uint32_t b0h = bh[na >> 1][(na & 1) * 2];
            uint32_t b1h = bh[na >> 1][(na & 1) * 2 + 1];
            uint32_t b0l = bl[na >> 1][(na & 1) * 2];
            uint32_t b1l = bl[na >> 1][(na & 1) * 2 + 1];
            mma16816(acc[na], ah, b0h, b1h);
            mma16816(acc[na], ah, b0l, b1l);
            mma16816(acc[na], al, b0h, b1h);
        }
    }

    // ---- epilogue. D-frag: c0,c1 -> (row l/4, col 2(l&3)+{0,1}); c2,c3 -> row+8
    int qr = lane >> 2, qc = lane & 3;
    int row0 = rowBase + mw + qr;
    int row1 = row0 + 8;
    bool ok0 = row0 < NN, ok1 = row1 < NN;
    float* o0 = Z + (size_t)row0 * DD + nw + qc * 2;
    float* o1 = Z + (size_t)row1 * DD + nw + qc * 2;

    if (mode == 2) {
        #pragma unroll
        for (int na = 0; na < 8; na++) {
            float* c = acc[na];
            if (ok0) *(float2*)(o0 + na * 8) =
                make_float2(fmaxf(c[0], 0.f), fmaxf(c[1], 0.f));
            if (ok1) *(float2*)(o1 + na * 8) =
                make_float2(fmaxf(c[2], 0.f), fmaxf(c[3], 0.f));
        }
    } else {
        float csum[16], csq[16];
        #pragma unroll
        for (int na = 0; na < 8; na++) {
            float2 bv = __ldg((const float2*)(bias + nw + na * 8 + qc * 2));
            float z0 = acc[na][0] + bv.x;
            float z1 = acc[na][1] + bv.y;
            float z2 = acc[na][2] + bv.x;
            float z3 = acc[na][3] + bv.y;
            if (ok0) *(float2*)(o0 + na * 8) = make_float2(z0, z1);
            if (ok1) *(float2*)(o1 + na * 8) = make_float2(z2, z3);
            float t0 = ok0 ? z0 : 0.f, t1 = ok0 ? z1 : 0.f;
            float t2 = ok1 ? z2 : 0.f, t3 = ok1 ? z3 : 0.f;
            csum[na * 2]     = t0 + t2;
            csum[na * 2 + 1] = t1 + t3;
            csq[na * 2]      = t0 * t0 + t2 * t2;
            csq[na * 2 + 1]  = t1 * t1 + t3 * t3;
        }
        // reduce over the 8 row-quads (lane bits 2..4)
        #pragma unroll
        for (int mask = 4; mask <= 16; mask <<= 1) {
            #pragma unroll
            for (int j = 0; j < 16; j++) {
                csum[j] += __shfl_xor_sync(0xffffffffu, csum[j], mask);
                csq[j]  += __shfl_xor_sync(0xffffffffu, csq[j], mask);
            }
        }
        int g = wid >> 1;  // 4 row groups; warps 2g/2g+1 cover disjoint cols
        if (lane < 4) {
            #pragma unroll
            for (int na = 0; na < 8; na++) {
                int col = nw + na * 8 + lane * 2;
                sSum[g * DD + col]     = csum[na * 2];
                sSum[g * DD + col + 1] = csum[na * 2 + 1];
                sSq [g * DD + col]     = csq[na * 2];
                sSq [g * DD + col + 1] = csq[na * 2 + 1];
            }
        }
        __syncthreads();
        if (tid < DD) {
            float s = sSum[tid] + sSum[DD + tid] + sSum[2 * DD + tid] + sSum[3 * DD + tid];
            atomicAdd(&gsum[tid], s);
        } else if (tid < 2 * DD) {
            int n = tid - DD;
            float s = sSq[n] + sSq[DD + n] + sSq[2 * DD + n] + sSq[3 * DD + n];
            atomicAdd(&gsq[n], s);
        }
    }
}

// ---------------- launch ----------------------------------------------------
extern "C" void kernel_launch(void* const* d_in, const int* in_sizes, int n_in,
                              void* d_out, int out_size) {
    const float* x   = (const float*)d_in[0];
    const void*  ei  = d_in[1];
    const float* W1  = (const float*)d_in[2];
    const float* b1  = (const float*)d_in[3];
    const float* g1  = (const float*)d_in[4];
    const float* be1 = (const float*)d_in[5];
    const float* W2  = (const float*)d_in[6];
    const float* b2  = (const float*)d_in[7];
    const float* g2  = (const float*)d_in[8];
    const float* be2 = (const float*)d_in[9];
    const float* W3  = (const float*)d_in[10];
    float* out = (float*)d_out;

    float *H, *Z, *s1, *q1, *s2, *q2;
    __nv_bfloat16 *Whi, *Wlo;
    int *pos;
    cudaGetSymbolAddress((void**)&H,   g_H);
    cudaGetSymbolAddress((void**)&Z,   g_Z);
    cudaGetSymbolAddress((void**)&s1,  g_sum1);
    cudaGetSymbolAddress((void**)&q1,  g_sq1);
    cudaGetSymbolAddress((void**)&s2,  g_sum2);
    cudaGetSymbolAddress((void**)&q2,  g_sq2);
    cudaGetSymbolAddress((void**)&Whi, g_Whi);
    cudaGetSymbolAddress((void**)&Wlo, g_Wlo);
    cudaGetSymbolAddress((void**)&pos, g_pos);

    cudaFuncSetAttribute(gemm_mma, cudaFuncAttributeMaxDynamicSharedMemorySize,
                         SMEM_BYTES);

    // 1) zero stats/counters ; detect edge dtype ; pre-split weights
    cudaMemsetAsync(pos, 0, NN * sizeof(int));
    prep<<<1, 128>>>((const unsigned long long*)ei);
    convW<<<(3 * DD * DD + 255) / 256, 256>>>(W1, W2, W3);

    // 2) CSR build + gather:  H = x + segment_sum(x[src] by dst)
    hist<<<(NE + 255) / 256, 256>>>(ei);
    blk_reduce<<<SCAN_BLKS, 1024>>>();
    scan_small<<<1, 128>>>();
    scan_final<<<SCAN_BLKS, 1024>>>();
    reorder<<<(NE + 255) / 256, 256>>>(ei);
    gather<<<(NN + 7) / 8, 256>>>((const float4*)x);

    int gblocks = (NN + MT - 1) / MT;  // 1563

    // 3) Z1 = H @ W1^T + b1, with column stats
    gemm_mma<<<gblocks, 256, SMEM_BYTES>>>(H, Whi, Wlo, b1,
                                           nullptr, nullptr, nullptr, nullptr,
                                           Z, s1, q1, 0);
    // 4) Z2 = relu(BN(Z1)) @ W2^T + b2, with column stats  (Z2 -> H buffer)
    gemm_mma<<<gblocks, 256, SMEM_BYTES>>>(Z, Whi + DD * DD, Wlo + DD * DD,
                                           b2, g1, be1, s1, q1,
                                           H, s2, q2, 1);
    // 5) out = relu( relu(BN(Z2)) @ W3^T )
    gemm_mma<<<gblocks, 256, SMEM_BYTES>>>(H, Whi + 2 * DD * DD, Wlo + 2 * DD * DD,
                                           nullptr, g2, be2, s2, q2,
                                           out, nullptr, nullptr, 2);
}